// round 3
// baseline (speedup 1.0000x reference)
#include <cuda_runtime.h>
#include <math.h>
#include <stdint.h>

#define B_SZ 2048
#define KIN  64
#define KOUT 64
#define BLK  256
#define KH   129

// Scratch (device globals: allocation-free per the rules)
__device__ float2   g_X[(size_t)B_SZ * KH * KIN];    // [b][f][j]  ~135 MB (viewed as X_ri floats)
__device__ float2   g_Y[(size_t)B_SZ * KH * KOUT];   // [b][f][i]  ~135 MB
__device__ uint32_t g_B[(size_t)KH * 128 * 128];     // [f][k][n] tf32 bits, 8.4 MB

// ---------------------------------------------------------------------------
// Radix-2 DIF 16-point FFT, fully unrolled, constant twiddles.
// ---------------------------------------------------------------------------
#define FC1 0.9238795325112867f
#define FS1 0.3826834323650898f
#define FC2 0.7071067811865476f

#define BF(i, j, cr, ci) {                                   \
    float ux = a[i].x, uy = a[i].y;                          \
    float vx = a[j].x, vy = a[j].y;                          \
    a[i].x = ux + vx; a[i].y = uy + vy;                      \
    float dx = ux - vx, dy = uy - vy;                        \
    a[j].x = dx * (cr) - dy * (ci);                          \
    a[j].y = dx * (ci) + dy * (cr); }

template<bool INV>
__device__ __forceinline__ void fft16_stages234(float2* a) {
    const float S = INV ? 1.0f : -1.0f;
    BF(0, 4, 1.0f, 0.0f)   BF(1, 5, FC2, S * FC2)
    BF(2, 6, 0.0f, S)      BF(3, 7, -FC2, S * FC2)
    BF(8, 12, 1.0f, 0.0f)  BF(9, 13, FC2, S * FC2)
    BF(10, 14, 0.0f, S)    BF(11, 15, -FC2, S * FC2)
    BF(0, 2, 1.0f, 0.0f)   BF(1, 3, 0.0f, S)
    BF(4, 6, 1.0f, 0.0f)   BF(5, 7, 0.0f, S)
    BF(8, 10, 1.0f, 0.0f)  BF(9, 11, 0.0f, S)
    BF(12, 14, 1.0f, 0.0f) BF(13, 15, 0.0f, S)
    BF(0, 1, 1.0f, 0.0f)   BF(2, 3, 1.0f, 0.0f)
    BF(4, 5, 1.0f, 0.0f)   BF(6, 7, 1.0f, 0.0f)
    BF(8, 9, 1.0f, 0.0f)   BF(10, 11, 1.0f, 0.0f)
    BF(12, 13, 1.0f, 0.0f) BF(14, 15, 1.0f, 0.0f)
}

template<bool INV>
__device__ __forceinline__ void fft16_full(float2* a) {
    const float S = INV ? 1.0f : -1.0f;
    BF(0, 8, 1.0f, 0.0f)      BF(1, 9, FC1, S * FS1)
    BF(2, 10, FC2, S * FC2)   BF(3, 11, FS1, S * FC1)
    BF(4, 12, 0.0f, S)        BF(5, 13, -FS1, S * FC1)
    BF(6, 14, -FC2, S * FC2)  BF(7, 15, -FC1, S * FS1)
    fft16_stages234<INV>(a);
}

__device__ __forceinline__ void fft16_real_fwd(const float* xr, float2* a) {
    const float tcr[8] = {1.0f, FC1, FC2, FS1, 0.0f, -FS1, -FC2, -FC1};
    const float tci[8] = {0.0f, -FS1, -FC2, -FC1, -1.0f, -FC1, -FC2, -FS1};
#pragma unroll
    for (int k = 0; k < 8; k++) {
        float s = xr[k] + xr[k + 8];
        float d = xr[k] - xr[k + 8];
        a[k]     = make_float2(s, 0.0f);
        a[k + 8] = make_float2(d * tcr[k], d * tci[k]);
    }
    fft16_stages234<false>(a);
}

#define REV4_LIST {0, 8, 4, 12, 2, 10, 6, 14, 1, 9, 5, 13, 3, 11, 7, 15}

__device__ __forceinline__ uint32_t f2tf32(float x) {
    uint32_t r;
    asm("cvt.rna.tf32.f32 %0, %1;" : "=r"(r) : "f"(x));
    return r;
}

// ---------------------------------------------------------------------------
// Kernel 1: build B_f[k][n] (2x-expanded complex W, conj), tf32-rounded.
//   k=2j+p (input re/im), n=2i+q (output re/im)
//   B[2j][2i]=Wr  B[2j+1][2i]=Wi  B[2j][2i+1]=-Wi  B[2j+1][2i+1]=Wr
// ---------------------------------------------------------------------------
__global__ void prep_b(const float* __restrict__ Wr, const float* __restrict__ Wi) {
    int idx = blockIdx.x * blockDim.x + threadIdx.x;
    if (idx >= KH * 128 * 128) return;
    int n = idx & 127;
    int k = (idx >> 7) & 127;
    int f = idx >> 14;
    int j = k >> 1, p = k & 1;
    int i = n >> 1, q = n & 1;
    size_t widx = ((size_t)i * KIN + j) * KH + f;
    float v;
    if (p == 0) v = (q == 0) ? Wr[widx] : -Wi[widx];
    else        v = (q == 0) ? Wi[widx] :  Wr[widx];
    g_B[idx] = f2tf32(v);
}

// ---------------------------------------------------------------------------
// Kernel 2: forward rFFT (256-pt, 16x16 Cooley-Tukey, radix-2 butterflies)
// ---------------------------------------------------------------------------
__global__ __launch_bounds__(256) void fft_fwd(const float* __restrict__ x) {
    __shared__ float2 tw[256];
    __shared__ float2 sbuf[16 * 16 * 17];

    const int rev[16] = REV4_LIST;
    int tid = threadIdx.x;
    {
        float s, c;
        sincospif(-(float)tid * (1.0f / 128.0f), &s, &c);
        tw[tid] = make_float2(c, s);
    }
    int cta = blockIdx.x;
    int b  = cta >> 2;
    int j0 = (cta & 3) << 4;
    int g  = tid >> 4;
    int t  = tid & 15;

    const float* xp = x + (size_t)b * 16384 + (size_t)(j0 + g) * 256 + t;
    float xr[16];
#pragma unroll
    for (int n1 = 0; n1 < 16; n1++) xr[n1] = xp[n1 * 16];

    __syncthreads();

    float2 a[16];
    fft16_real_fwd(xr, a);
#pragma unroll
    for (int f1 = 0; f1 < 16; f1++) {
        float2 A = a[rev[f1]];
        float2 t2 = tw[(t * f1) & 255];
        float pr = A.x * t2.x - A.y * t2.y;
        float pi = A.x * t2.y + A.y * t2.x;
        sbuf[g * 272 + t * 17 + f1] = make_float2(pr, pi);
    }
    __syncthreads();

    float2 c[16];
#pragma unroll
    for (int n2 = 0; n2 < 16; n2++) c[n2] = sbuf[g * 272 + n2 * 17 + t];
    __syncthreads();

    fft16_full<false>(c);
    {
        int f1 = t;
#pragma unroll
        for (int f2 = 0; f2 < 16; f2++) {
            int f = f1 + (f2 << 4);
            if (f <= 128) sbuf[g * 129 + f] = c[rev[f2]];
        }
    }
    __syncthreads();

    for (int k = tid; k < 16 * 129; k += 256) {
        int jg = k & 15;
        int f  = k >> 4;
        g_X[((size_t)b * KH + f) * KIN + j0 + jg] = sbuf[jg * 129 + f];
    }
}

// ---------------------------------------------------------------------------
// Kernel 3: tensor-core real GEMM per bin: Y_ri[128b x 128n] += A_ri * B_f
// mma.sync m16n8k8 tf32. CTA: (f, 128-row b-tile). 8 warps, warp tile 32x64.
// ---------------------------------------------------------------------------
__global__ __launch_bounds__(256) void cgemm_tc() {
    extern __shared__ uint32_t smu[];
    uint32_t* sA = smu;            // [128 m][132]
    uint32_t* sB = smu + 128 * 132; // [128 k][132]

    int f  = blockIdx.y;
    int b0 = blockIdx.x << 7;
    int tid = threadIdx.x;

    const float* Xf = (const float*)g_X;

    // Stage A (convert fp32 -> tf32 RNA), vectorized
    for (int e = tid; e < 4096; e += 256) {
        int m  = e >> 5;
        int k4 = (e & 31) << 2;
        const float4* src = (const float4*)(Xf + ((size_t)(b0 + m) * KH + f) * 128);
        float4 v = src[e & 31];
        uint4 w;
        w.x = f2tf32(v.x); w.y = f2tf32(v.y); w.z = f2tf32(v.z); w.w = f2tf32(v.w);
        *(uint4*)&sA[m * 132 + k4] = w;
    }
    // Stage B (already tf32 bits)
    {
        const uint4* src = (const uint4*)(g_B + (size_t)f * 16384);
        for (int e = tid; e < 4096; e += 256) {
            int k  = e >> 5;
            int n4 = (e & 31) << 2;
            *(uint4*)&sB[k * 132 + n4] = src[e];
        }
    }
    __syncthreads();

    int lane = tid & 31;
    int warp = tid >> 5;
    int gid = lane >> 2;   // 0..7
    int tig = lane & 3;    // 0..3
    int wm = warp & 3;     // m-tile: rows wm*32 .. +32
    int wn = warp >> 2;    // n-tile: cols wn*64 .. +64

    float acc[2][8][4];
#pragma unroll
    for (int mt = 0; mt < 2; mt++)
#pragma unroll
        for (int nt = 0; nt < 8; nt++)
#pragma unroll
            for (int r = 0; r < 4; r++) acc[mt][nt][r] = 0.f;

    int arow0 = wm * 32 + gid;
    int bcol  = wn * 64 + gid;

#pragma unroll 4
    for (int k0 = 0; k0 < 128; k0 += 8) {
        uint32_t afr[2][4];
#pragma unroll
        for (int mt = 0; mt < 2; mt++) {
            int r0 = arow0 + mt * 16;
            afr[mt][0] = sA[r0 * 132 + k0 + tig];
            afr[mt][1] = sA[(r0 + 8) * 132 + k0 + tig];
            afr[mt][2] = sA[r0 * 132 + k0 + tig + 4];
            afr[mt][3] = sA[(r0 + 8) * 132 + k0 + tig + 4];
        }
        uint32_t bfr[8][2];
#pragma unroll
        for (int nt = 0; nt < 8; nt++) {
            int c0 = bcol + nt * 8;
            bfr[nt][0] = sB[(k0 + tig) * 132 + c0];
            bfr[nt][1] = sB[(k0 + tig + 4) * 132 + c0];
        }
#pragma unroll
        for (int mt = 0; mt < 2; mt++)
#pragma unroll
            for (int nt = 0; nt < 8; nt++) {
                asm volatile(
                    "mma.sync.aligned.m16n8k8.row.col.f32.tf32.tf32.f32 "
                    "{%0,%1,%2,%3}, {%4,%5,%6,%7}, {%8,%9}, {%0,%1,%2,%3};\n"
                    : "+f"(acc[mt][nt][0]), "+f"(acc[mt][nt][1]),
                      "+f"(acc[mt][nt][2]), "+f"(acc[mt][nt][3])
                    : "r"(afr[mt][0]), "r"(afr[mt][1]), "r"(afr[mt][2]), "r"(afr[mt][3]),
                      "r"(bfr[nt][0]), "r"(bfr[nt][1]));
            }
    }

    // Epilogue: write Y_ri (float2 pairs: n even = re, n odd = im)
    float* Yf = (float*)g_Y;
#pragma unroll
    for (int mt = 0; mt < 2; mt++) {
        int mrow = wm * 32 + mt * 16 + gid;
        size_t base0 = ((size_t)(b0 + mrow) * KH + f) * 128;
        size_t base1 = ((size_t)(b0 + mrow + 8) * KH + f) * 128;
#pragma unroll
        for (int nt = 0; nt < 8; nt++) {
            int n = wn * 64 + nt * 8 + (tig << 1);
            *(float2*)(Yf + base0 + n) = make_float2(acc[mt][nt][0], acc[mt][nt][1]);
            *(float2*)(Yf + base1 + n) = make_float2(acc[mt][nt][2], acc[mt][nt][3]);
        }
    }
}

// ---------------------------------------------------------------------------
// Kernel 4: inverse rFFT, real output, scale 1/256.
// ---------------------------------------------------------------------------
__global__ __launch_bounds__(256) void fft_inv(float* __restrict__ out) {
    __shared__ float2 tw[256];
    __shared__ float2 sbuf[16 * 16 * 17];

    const int rev[16] = REV4_LIST;
    int tid = threadIdx.x;
    {
        float s, c;
        sincospif(-(float)tid * (1.0f / 128.0f), &s, &c);
        tw[tid] = make_float2(c, s);
    }
    int cta = blockIdx.x;
    int b  = cta >> 2;
    int i0 = (cta & 3) << 4;
    int g  = tid >> 4;
    int t  = tid & 15;

    for (int k = tid; k < 129 * 16; k += 256) {
        int gg = k & 15;
        int f  = k >> 4;
        sbuf[f * 17 + gg] = g_Y[((size_t)b * KH + f) * KOUT + i0 + gg];
    }
    __syncthreads();

    int f1 = t;
    float2 a[16];
#pragma unroll
    for (int f2 = 0; f2 < 16; f2++) {
        int f = f1 + (f2 << 4);
        if (f <= 128) {
            a[f2] = sbuf[f * 17 + g];
        } else {
            float2 v = sbuf[(256 - f) * 17 + g];
            a[f2] = make_float2(v.x, -v.y);
        }
    }
    __syncthreads();

    fft16_full<true>(a);
#pragma unroll
    for (int t1 = 0; t1 < 16; t1++) {
        float2 B = a[rev[t1]];
        float2 t2 = tw[(f1 * t1) & 255];
        float pr =  B.x * t2.x + B.y * t2.y;
        float pi = -B.x * t2.y + B.y * t2.x;
        sbuf[g * 272 + f1 * 17 + t1] = make_float2(pr, pi);
    }
    __syncthreads();

    int t1 = t;
    float2 bb[16];
#pragma unroll
    for (int f1i = 0; f1i < 16; f1i++) bb[f1i] = sbuf[g * 272 + f1i * 17 + t1];
    __syncthreads();

    fft16_full<true>(bb);

    float* outs = (float*)sbuf;
#pragma unroll
    for (int t2 = 0; t2 < 16; t2++) {
        outs[g * 256 + t1 + (t2 << 4)] = bb[rev[t2]].x * (1.0f / 256.0f);
    }
    __syncthreads();

    float* op = out + (size_t)b * 16384 + (size_t)i0 * 256;
    for (int k = tid; k < 4096; k += 256) op[k] = outs[k];
}

// ---------------------------------------------------------------------------
extern "C" void kernel_launch(void* const* d_in, const int* in_sizes, int n_in,
                              void* d_out, int out_size) {
    const float* x  = (const float*)d_in[0];
    const float* Wr = (const float*)d_in[1];
    const float* Wi = (const float*)d_in[2];
    float* out = (float*)d_out;

    const int smem_gemm = 2 * 128 * 132 * 4; // 135168
    cudaFuncSetAttribute(cgemm_tc, cudaFuncAttributeMaxDynamicSharedMemorySize, smem_gemm);

    prep_b<<<(KH * 128 * 128 + 255) / 256, 256>>>(Wr, Wi);
    fft_fwd<<<B_SZ * (KIN / 16), 256>>>(x);
    cgemm_tc<<<dim3(16, KH), 256, smem_gemm>>>();
    fft_inv<<<B_SZ * (KOUT / 16), 256>>>(out);
}

// round 5
// speedup vs baseline: 1.5660x; 1.5660x over previous
#include <cuda_runtime.h>
#include <math.h>
#include <stdint.h>

#define B_SZ 2048
#define KIN  64
#define KOUT 64
#define KH   129

// Scratch (device globals: allocation-free per the rules)
__device__ float2 g_X[(size_t)B_SZ * KH * KIN];    // [b][f][j] ~135 MB (tf32-rounded floats)
__device__ float2 g_Y[(size_t)B_SZ * KH * KOUT];   // [b][f][i] ~135 MB
__device__ float  g_B[(size_t)KH * 16384];         // [f][k][n] tf32-rounded, 8.4 MB

// ===========================================================================
// helpers
// ===========================================================================
__device__ __forceinline__ uint32_t smem_to_u32(const void* p) {
    uint32_t a;
    asm("{ .reg .u64 t; cvta.to.shared.u64 t, %1; cvt.u32.u64 %0, t; }" : "=r"(a) : "l"(p));
    return a;
}
__device__ __forceinline__ uint32_t f2tf32(float x) {
    uint32_t r;
    asm("cvt.rna.tf32.f32 %0, %1;" : "=r"(r) : "f"(x));
    return r;
}
__device__ __forceinline__ void cp_async16(uint32_t dst, const void* src) {
    asm volatile("cp.async.cg.shared.global [%0], [%1], 16;" :: "r"(dst), "l"(src));
}
#define CP_COMMIT() asm volatile("cp.async.commit_group;" ::: "memory")
#define CP_WAIT1()  asm volatile("cp.async.wait_group 1;" ::: "memory")

// ===========================================================================
// Radix-2 DIF 16-point FFT machinery
// ===========================================================================
#define FC1 0.9238795325112867f
#define FS1 0.3826834323650898f
#define FC2 0.7071067811865476f
#define BF(i, j, cr, ci) {                                   \
    float ux = a[i].x, uy = a[i].y;                          \
    float vx = a[j].x, vy = a[j].y;                          \
    a[i].x = ux + vx; a[i].y = uy + vy;                      \
    float dx = ux - vx, dy = uy - vy;                        \
    a[j].x = dx * (cr) - dy * (ci);                          \
    a[j].y = dx * (ci) + dy * (cr); }

template<bool INV>
__device__ __forceinline__ void fft16_stages234(float2* a) {
    const float S = INV ? 1.0f : -1.0f;
    BF(0, 4, 1.0f, 0.0f)   BF(1, 5, FC2, S * FC2)
    BF(2, 6, 0.0f, S)      BF(3, 7, -FC2, S * FC2)
    BF(8, 12, 1.0f, 0.0f)  BF(9, 13, FC2, S * FC2)
    BF(10, 14, 0.0f, S)    BF(11, 15, -FC2, S * FC2)
    BF(0, 2, 1.0f, 0.0f)   BF(1, 3, 0.0f, S)
    BF(4, 6, 1.0f, 0.0f)   BF(5, 7, 0.0f, S)
    BF(8, 10, 1.0f, 0.0f)  BF(9, 11, 0.0f, S)
    BF(12, 14, 1.0f, 0.0f) BF(13, 15, 0.0f, S)
    BF(0, 1, 1.0f, 0.0f)   BF(2, 3, 1.0f, 0.0f)
    BF(4, 5, 1.0f, 0.0f)   BF(6, 7, 1.0f, 0.0f)
    BF(8, 9, 1.0f, 0.0f)   BF(10, 11, 1.0f, 0.0f)
    BF(12, 13, 1.0f, 0.0f) BF(14, 15, 1.0f, 0.0f)
}
template<bool INV>
__device__ __forceinline__ void fft16_full(float2* a) {
    const float S = INV ? 1.0f : -1.0f;
    BF(0, 8, 1.0f, 0.0f)      BF(1, 9, FC1, S * FS1)
    BF(2, 10, FC2, S * FC2)   BF(3, 11, FS1, S * FC1)
    BF(4, 12, 0.0f, S)        BF(5, 13, -FS1, S * FC1)
    BF(6, 14, -FC2, S * FC2)  BF(7, 15, -FC1, S * FS1)
    fft16_stages234<INV>(a);
}
__device__ __forceinline__ void fft16_real_fwd(const float* xr, float2* a) {
    const float tcr[8] = {1.0f, FC1, FC2, FS1, 0.0f, -FS1, -FC2, -FC1};
    const float tci[8] = {0.0f, -FS1, -FC2, -FC1, -1.0f, -FC1, -FC2, -FS1};
#pragma unroll
    for (int k = 0; k < 8; k++) {
        float s = xr[k] + xr[k + 8];
        float d = xr[k] - xr[k + 8];
        a[k]     = make_float2(s, 0.0f);
        a[k + 8] = make_float2(d * tcr[k], d * tci[k]);
    }
    fft16_stages234<false>(a);
}
#define REV4_LIST {0, 8, 4, 12, 2, 10, 6, 14, 1, 9, 5, 13, 3, 11, 7, 15}

// ---------------------------------------------------------------------------
// Kernel 1: build B_f[k][n] (2x-expanded complex conj W), tf32-rounded fp32
//   k=2j+p (input re/im), n=2i+q (output re/im)
// ---------------------------------------------------------------------------
__global__ void prep_b(const float* __restrict__ Wr, const float* __restrict__ Wi) {
    int idx = blockIdx.x * blockDim.x + threadIdx.x;
    if (idx >= KH * 16384) return;
    int n = idx & 127;
    int k = (idx >> 7) & 127;
    int f = idx >> 14;
    int j = k >> 1, p = k & 1;
    int i = n >> 1, q = n & 1;
    size_t widx = ((size_t)i * KIN + j) * KH + f;
    float v;
    if (p == 0) v = (q == 0) ? Wr[widx] : -Wi[widx];
    else        v = (q == 0) ? Wi[widx] :  Wr[widx];
    g_B[idx] = __uint_as_float(f2tf32(v));
}

// ---------------------------------------------------------------------------
// Kernel 2: forward rFFT; output tf32-RNA-rounded (GEMM A operand)
// ---------------------------------------------------------------------------
__global__ __launch_bounds__(256) void fft_fwd(const float* __restrict__ x) {
    __shared__ float2 tw[256];
    __shared__ float2 sbuf[16 * 16 * 17];

    const int rev[16] = REV4_LIST;
    int tid = threadIdx.x;
    {
        float s, c;
        sincospif(-(float)tid * (1.0f / 128.0f), &s, &c);
        tw[tid] = make_float2(c, s);
    }
    int cta = blockIdx.x;
    int b  = cta >> 2;
    int j0 = (cta & 3) << 4;
    int g  = tid >> 4;
    int t  = tid & 15;

    const float* xp = x + (size_t)b * 16384 + (size_t)(j0 + g) * 256 + t;
    float xr[16];
#pragma unroll
    for (int n1 = 0; n1 < 16; n1++) xr[n1] = xp[n1 * 16];
    __syncthreads();

    float2 a[16];
    fft16_real_fwd(xr, a);
#pragma unroll
    for (int f1 = 0; f1 < 16; f1++) {
        float2 A = a[rev[f1]];
        float2 t2 = tw[(t * f1) & 255];
        float pr = A.x * t2.x - A.y * t2.y;
        float pi = A.x * t2.y + A.y * t2.x;
        sbuf[g * 272 + t * 17 + f1] = make_float2(pr, pi);
    }
    __syncthreads();

    float2 c[16];
#pragma unroll
    for (int n2 = 0; n2 < 16; n2++) c[n2] = sbuf[g * 272 + n2 * 17 + t];
    __syncthreads();

    fft16_full<false>(c);
    {
        int f1 = t;
#pragma unroll
        for (int f2 = 0; f2 < 16; f2++) {
            int f = f1 + (f2 << 4);
            if (f <= 128) sbuf[g * 129 + f] = c[rev[f2]];
        }
    }
    __syncthreads();

    for (int k = tid; k < 16 * 129; k += 256) {
        int jg = k & 15;
        int f  = k >> 4;
        float2 v = sbuf[jg * 129 + f];
        v.x = __uint_as_float(f2tf32(v.x));
        v.y = __uint_as_float(f2tf32(v.y));
        g_X[((size_t)b * KH + f) * KIN + j0 + jg] = v;
    }
}

// ---------------------------------------------------------------------------
// Kernel 3: pipelined persistent tf32 mma.sync GEMM.
// CTA = one f. B resident; A double-buffered via cp.async over 16 b-tiles.
// ---------------------------------------------------------------------------
#define SM_B  0
#define SM_A0 67584
#define SM_A1 (67584 * 2)
#define SM_TOT (67584 * 3)

__global__ __launch_bounds__(256, 1) void cgemm_pipe() {
    extern __shared__ char smem[];
    uint32_t smem_base = smem_to_u32(smem);
    float* sB = (float*)(smem + SM_B);

    int f = blockIdx.x;
    int tid = threadIdx.x;
    const float* Xf = (const float*)g_X;

    // Stage B (resident): [k][132]
    {
        const float4* src = (const float4*)(g_B + (size_t)f * 16384);
        for (int e = tid; e < 4096; e += 256) {
            int k  = e >> 5;
            int n4 = (e & 31) << 2;
            *(float4*)&sB[k * 132 + n4] = src[e];
        }
    }

    // A loader: tile bt -> buffer buf via cp.async (16B chunks)
    auto loadA = [&](int bt, int buf) {
        uint32_t base = smem_base + (buf ? SM_A1 : SM_A0);
        int m = tid >> 4;             // 2 rows per pass below
        int c = (tid & 15) << 1;      // float4 index pairs
#pragma unroll
        for (int rr = 0; rr < 8; rr++) {
            int row = m + rr * 16;
            const float* src = Xf + ((size_t)(bt * 128 + row) * KH + f) * 128;
            uint32_t dst = base + (uint32_t)(row * 132 + c * 4) * 4;
            cp_async16(dst, src + c * 4);
            cp_async16(dst + 16, src + c * 4 + 4);
        }
    };

    int lane = tid & 31;
    int warp = tid >> 5;
    int gid = lane >> 2;
    int tig = lane & 3;
    int wm = warp & 3;
    int wn = warp >> 2;
    int arow0 = wm * 32 + gid;
    int bcol  = wn * 64 + gid;

    loadA(0, 0);
    CP_COMMIT();

    for (int it = 0; it < 16; it++) {
        if (it + 1 < 16) loadA(it + 1, (it + 1) & 1);
        CP_COMMIT();
        CP_WAIT1();
        __syncthreads();

        const float* sA = (const float*)(smem + ((it & 1) ? SM_A1 : SM_A0));

        float acc[2][8][4];
#pragma unroll
        for (int mt = 0; mt < 2; mt++)
#pragma unroll
            for (int nt = 0; nt < 8; nt++)
#pragma unroll
                for (int r = 0; r < 4; r++) acc[mt][nt][r] = 0.f;

#pragma unroll 4
        for (int k0 = 0; k0 < 128; k0 += 8) {
            uint32_t afr[2][4];
#pragma unroll
            for (int mt = 0; mt < 2; mt++) {
                int r0 = arow0 + mt * 16;
                afr[mt][0] = __float_as_uint(sA[r0 * 132 + k0 + tig]);
                afr[mt][1] = __float_as_uint(sA[(r0 + 8) * 132 + k0 + tig]);
                afr[mt][2] = __float_as_uint(sA[r0 * 132 + k0 + tig + 4]);
                afr[mt][3] = __float_as_uint(sA[(r0 + 8) * 132 + k0 + tig + 4]);
            }
            uint32_t bfr[8][2];
#pragma unroll
            for (int nt = 0; nt < 8; nt++) {
                int c0 = bcol + nt * 8;
                bfr[nt][0] = __float_as_uint(sB[(k0 + tig) * 132 + c0]);
                bfr[nt][1] = __float_as_uint(sB[(k0 + tig + 4) * 132 + c0]);
            }
#pragma unroll
            for (int mt = 0; mt < 2; mt++)
#pragma unroll
                for (int nt = 0; nt < 8; nt++) {
                    asm volatile(
                        "mma.sync.aligned.m16n8k8.row.col.f32.tf32.tf32.f32 "
                        "{%0,%1,%2,%3}, {%4,%5,%6,%7}, {%8,%9}, {%0,%1,%2,%3};\n"
                        : "+f"(acc[mt][nt][0]), "+f"(acc[mt][nt][1]),
                          "+f"(acc[mt][nt][2]), "+f"(acc[mt][nt][3])
                        : "r"(afr[mt][0]), "r"(afr[mt][1]), "r"(afr[mt][2]), "r"(afr[mt][3]),
                          "r"(bfr[nt][0]), "r"(bfr[nt][1]));
                }
        }

        // Epilogue: Y_ri rows (coalesced 32B per quad)
        float* Yf = (float*)g_Y;
        int b0 = it * 128;
#pragma unroll
        for (int mt = 0; mt < 2; mt++) {
            int mrow = wm * 32 + mt * 16 + gid;
            size_t base0 = ((size_t)(b0 + mrow) * KH + f) * 128;
            size_t base1 = ((size_t)(b0 + mrow + 8) * KH + f) * 128;
#pragma unroll
            for (int nt = 0; nt < 8; nt++) {
                int n = wn * 64 + nt * 8 + (tig << 1);
                *(float2*)(Yf + base0 + n) = make_float2(acc[mt][nt][0], acc[mt][nt][1]);
                *(float2*)(Yf + base1 + n) = make_float2(acc[mt][nt][2], acc[mt][nt][3]);
            }
        }
        __syncthreads(); // buffer consumed before next overwrite
    }
}

// ---------------------------------------------------------------------------
// Kernel 4: inverse rFFT (unchanged)
// ---------------------------------------------------------------------------
__global__ __launch_bounds__(256) void fft_inv(float* __restrict__ out) {
    __shared__ float2 tw[256];
    __shared__ float2 sbuf[16 * 16 * 17];

    const int rev[16] = REV4_LIST;
    int tid = threadIdx.x;
    {
        float s, c;
        sincospif(-(float)tid * (1.0f / 128.0f), &s, &c);
        tw[tid] = make_float2(c, s);
    }
    int cta = blockIdx.x;
    int b  = cta >> 2;
    int i0 = (cta & 3) << 4;
    int g  = tid >> 4;
    int t  = tid & 15;

    for (int k = tid; k < 129 * 16; k += 256) {
        int gg = k & 15;
        int f  = k >> 4;
        sbuf[f * 17 + gg] = g_Y[((size_t)b * KH + f) * KOUT + i0 + gg];
    }
    __syncthreads();

    int f1 = t;
    float2 a[16];
#pragma unroll
    for (int f2 = 0; f2 < 16; f2++) {
        int f = f1 + (f2 << 4);
        if (f <= 128) {
            a[f2] = sbuf[f * 17 + g];
        } else {
            float2 v = sbuf[(256 - f) * 17 + g];
            a[f2] = make_float2(v.x, -v.y);
        }
    }
    __syncthreads();

    fft16_full<true>(a);
#pragma unroll
    for (int t1 = 0; t1 < 16; t1++) {
        float2 B = a[rev[t1]];
        float2 t2 = tw[(f1 * t1) & 255];
        float pr =  B.x * t2.x + B.y * t2.y;
        float pi = -B.x * t2.y + B.y * t2.x;
        sbuf[g * 272 + f1 * 17 + t1] = make_float2(pr, pi);
    }
    __syncthreads();

    int t1 = t;
    float2 bb[16];
#pragma unroll
    for (int f1i = 0; f1i < 16; f1i++) bb[f1i] = sbuf[g * 272 + f1i * 17 + t1];
    __syncthreads();

    fft16_full<true>(bb);

    float* outs = (float*)sbuf;
#pragma unroll
    for (int t2 = 0; t2 < 16; t2++) {
        outs[g * 256 + t1 + (t2 << 4)] = bb[rev[t2]].x * (1.0f / 256.0f);
    }
    __syncthreads();

    float* op = out + (size_t)b * 16384 + (size_t)i0 * 256;
    for (int k = tid; k < 4096; k += 256) op[k] = outs[k];
}

// ---------------------------------------------------------------------------
extern "C" void kernel_launch(void* const* d_in, const int* in_sizes, int n_in,
                              void* d_out, int out_size) {
    const float* x  = (const float*)d_in[0];
    const float* Wr = (const float*)d_in[1];
    const float* Wi = (const float*)d_in[2];
    float* out = (float*)d_out;

    cudaFuncSetAttribute(cgemm_pipe, cudaFuncAttributeMaxDynamicSharedMemorySize, SM_TOT);

    prep_b<<<(KH * 16384 + 255) / 256, 256>>>(Wr, Wi);
    fft_fwd<<<B_SZ * (KIN / 16), 256>>>(x);
    cgemm_pipe<<<KH, 256, SM_TOT>>>();
    fft_inv<<<B_SZ * (KOUT / 16), 256>>>(out);
}

// round 6
// speedup vs baseline: 1.8737x; 1.1965x over previous
#include <cuda_runtime.h>
#include <cuda_fp16.h>
#include <math.h>
#include <stdint.h>

#define B_SZ 2048
#define KIN  64
#define KOUT 64
#define KH   129

// Scratch (device globals: allocation-free per the rules)
__device__ __align__(256) __half2 g_Xh[(size_t)B_SZ * KH * KIN];   // [b][f][j] ~67 MB
__device__ __align__(256) __half2 g_Yh[(size_t)B_SZ * KH * KOUT];  // [b][f][i] ~67 MB
__device__ __align__(256) __half  g_Bh[(size_t)KH * 16384];        // [f][n][k] ~4.2 MB

// ===========================================================================
// helpers
// ===========================================================================
__device__ __forceinline__ uint32_t smem_to_u32(const void* p) {
    uint32_t a;
    asm("{ .reg .u64 t; cvta.to.shared.u64 t, %1; cvt.u32.u64 %0, t; }" : "=r"(a) : "l"(p));
    return a;
}
__device__ __forceinline__ void cp_async16(uint32_t dst, const void* src) {
    asm volatile("cp.async.cg.shared.global [%0], [%1], 16;" :: "r"(dst), "l"(src));
}
#define CP_COMMIT() asm volatile("cp.async.commit_group;" ::: "memory")
#define CP_WAIT1()  asm volatile("cp.async.wait_group 1;" ::: "memory")

#define LDSM_X4(r0, r1, r2, r3, addr) \
    asm volatile("ldmatrix.sync.aligned.m8n8.x4.shared.b16 {%0,%1,%2,%3}, [%4];" \
        : "=r"(r0), "=r"(r1), "=r"(r2), "=r"(r3) : "r"(addr))

#define HMMA16(d, a, b0v, b1v) \
    asm volatile("mma.sync.aligned.m16n8k16.row.col.f32.f16.f16.f32 " \
        "{%0,%1,%2,%3}, {%4,%5,%6,%7}, {%8,%9}, {%0,%1,%2,%3};" \
        : "+f"((d)[0]), "+f"((d)[1]), "+f"((d)[2]), "+f"((d)[3]) \
        : "r"((a)[0]), "r"((a)[1]), "r"((a)[2]), "r"((a)[3]), "r"(b0v), "r"(b1v))

// ===========================================================================
// Radix-2 DIF 16-point FFT machinery
// ===========================================================================
#define FC1 0.9238795325112867f
#define FS1 0.3826834323650898f
#define FC2 0.7071067811865476f
#define BF(i, j, cr, ci) {                                   \
    float ux = a[i].x, uy = a[i].y;                          \
    float vx = a[j].x, vy = a[j].y;                          \
    a[i].x = ux + vx; a[i].y = uy + vy;                      \
    float dx = ux - vx, dy = uy - vy;                        \
    a[j].x = dx * (cr) - dy * (ci);                          \
    a[j].y = dx * (ci) + dy * (cr); }

template<bool INV>
__device__ __forceinline__ void fft16_stages234(float2* a) {
    const float S = INV ? 1.0f : -1.0f;
    BF(0, 4, 1.0f, 0.0f)   BF(1, 5, FC2, S * FC2)
    BF(2, 6, 0.0f, S)      BF(3, 7, -FC2, S * FC2)
    BF(8, 12, 1.0f, 0.0f)  BF(9, 13, FC2, S * FC2)
    BF(10, 14, 0.0f, S)    BF(11, 15, -FC2, S * FC2)
    BF(0, 2, 1.0f, 0.0f)   BF(1, 3, 0.0f, S)
    BF(4, 6, 1.0f, 0.0f)   BF(5, 7, 0.0f, S)
    BF(8, 10, 1.0f, 0.0f)  BF(9, 11, 0.0f, S)
    BF(12, 14, 1.0f, 0.0f) BF(13, 15, 0.0f, S)
    BF(0, 1, 1.0f, 0.0f)   BF(2, 3, 1.0f, 0.0f)
    BF(4, 5, 1.0f, 0.0f)   BF(6, 7, 1.0f, 0.0f)
    BF(8, 9, 1.0f, 0.0f)   BF(10, 11, 1.0f, 0.0f)
    BF(12, 13, 1.0f, 0.0f) BF(14, 15, 1.0f, 0.0f)
}
template<bool INV>
__device__ __forceinline__ void fft16_full(float2* a) {
    const float S = INV ? 1.0f : -1.0f;
    BF(0, 8, 1.0f, 0.0f)      BF(1, 9, FC1, S * FS1)
    BF(2, 10, FC2, S * FC2)   BF(3, 11, FS1, S * FC1)
    BF(4, 12, 0.0f, S)        BF(5, 13, -FS1, S * FC1)
    BF(6, 14, -FC2, S * FC2)  BF(7, 15, -FC1, S * FS1)
    fft16_stages234<INV>(a);
}
__device__ __forceinline__ void fft16_real_fwd(const float* xr, float2* a) {
    const float tcr[8] = {1.0f, FC1, FC2, FS1, 0.0f, -FS1, -FC2, -FC1};
    const float tci[8] = {0.0f, -FS1, -FC2, -FC1, -1.0f, -FC1, -FC2, -FS1};
#pragma unroll
    for (int k = 0; k < 8; k++) {
        float s = xr[k] + xr[k + 8];
        float d = xr[k] - xr[k + 8];
        a[k]     = make_float2(s, 0.0f);
        a[k + 8] = make_float2(d * tcr[k], d * tci[k]);
    }
    fft16_stages234<false>(a);
}
#define REV4_LIST {0, 8, 4, 12, 2, 10, 6, 14, 1, 9, 5, 13, 3, 11, 7, 15}

// ---------------------------------------------------------------------------
// Kernel 1: build B_f[n][k] half (2x-expanded complex conj W)
//   k=2j+p (input re/im), n=2i+q (output re/im)
// ---------------------------------------------------------------------------
__global__ void prep_b(const float* __restrict__ Wr, const float* __restrict__ Wi) {
    int idx = blockIdx.x * blockDim.x + threadIdx.x;
    if (idx >= KH * 16384) return;
    int k = idx & 127;
    int n = (idx >> 7) & 127;
    int f = idx >> 14;
    int j = k >> 1, p = k & 1;
    int i = n >> 1, q = n & 1;
    size_t widx = ((size_t)i * KIN + j) * KH + f;
    float v;
    if (p == 0) v = (q == 0) ? Wr[widx] : -Wi[widx];
    else        v = (q == 0) ? Wi[widx] :  Wr[widx];
    g_Bh[idx] = __float2half_rn(v);
}

// ---------------------------------------------------------------------------
// Kernel 2: forward rFFT; output half2 complex
// ---------------------------------------------------------------------------
__global__ __launch_bounds__(256) void fft_fwd(const float* __restrict__ x) {
    __shared__ float2 tw[256];
    __shared__ float2 sbuf[16 * 16 * 17];

    const int rev[16] = REV4_LIST;
    int tid = threadIdx.x;
    {
        float s, c;
        sincospif(-(float)tid * (1.0f / 128.0f), &s, &c);
        tw[tid] = make_float2(c, s);
    }
    int cta = blockIdx.x;
    int b  = cta >> 2;
    int j0 = (cta & 3) << 4;
    int g  = tid >> 4;
    int t  = tid & 15;

    const float* xp = x + (size_t)b * 16384 + (size_t)(j0 + g) * 256 + t;
    float xr[16];
#pragma unroll
    for (int n1 = 0; n1 < 16; n1++) xr[n1] = xp[n1 * 16];
    __syncthreads();

    float2 a[16];
    fft16_real_fwd(xr, a);
#pragma unroll
    for (int f1 = 0; f1 < 16; f1++) {
        float2 A = a[rev[f1]];
        float2 t2 = tw[(t * f1) & 255];
        float pr = A.x * t2.x - A.y * t2.y;
        float pi = A.x * t2.y + A.y * t2.x;
        sbuf[g * 272 + t * 17 + f1] = make_float2(pr, pi);
    }
    __syncthreads();

    float2 c[16];
#pragma unroll
    for (int n2 = 0; n2 < 16; n2++) c[n2] = sbuf[g * 272 + n2 * 17 + t];
    __syncthreads();

    fft16_full<false>(c);
    {
        int f1 = t;
#pragma unroll
        for (int f2 = 0; f2 < 16; f2++) {
            int f = f1 + (f2 << 4);
            if (f <= 128) sbuf[g * 129 + f] = c[rev[f2]];
        }
    }
    __syncthreads();

    for (int k = tid; k < 16 * 129; k += 256) {
        int jg = k & 15;
        int f  = k >> 4;
        float2 v = sbuf[jg * 129 + f];
        g_Xh[((size_t)b * KH + f) * KIN + j0 + jg] = __floats2half2_rn(v.x, v.y);
    }
}

// ---------------------------------------------------------------------------
// Kernel 3: pipelined persistent fp16 mma.sync GEMM, ldmatrix fragments.
// CTA = one f. B resident; A double-buffered via cp.async over 16 b-tiles.
// smem pitch: 136 halfs (272 B) -> conflict-free ldmatrix phases.
// ---------------------------------------------------------------------------
#define SMB   0
#define SMA0  (128 * 272)
#define SMA1  (2 * 128 * 272)
#define SMTOT (3 * 128 * 272)   // 104448 B

__global__ __launch_bounds__(256, 1) void cgemm_h() {
    extern __shared__ char smem[];
    uint32_t sb = smem_to_u32(smem);
    int f = blockIdx.x;
    int tid = threadIdx.x;

    // Stage B (resident), rows n: 256 B each
    {
        int r = tid & 127, h = tid >> 7;
        const char* src = (const char*)(g_Bh + (size_t)f * 16384) + r * 256 + h * 128;
        uint32_t dst = sb + SMB + r * 272 + h * 128;
#pragma unroll
        for (int cc = 0; cc < 8; cc++) cp_async16(dst + cc * 16, src + cc * 16);
    }

    auto loadA = [&](int bt, int buf) {
        int r = tid & 127, h = tid >> 7;
        const char* src = (const char*)(g_Xh + ((size_t)(bt * 128 + r) * KH + f) * KIN) + h * 128;
        uint32_t dst = sb + (buf ? SMA1 : SMA0) + r * 272 + h * 128;
#pragma unroll
        for (int cc = 0; cc < 8; cc++) cp_async16(dst + cc * 16, src + cc * 16);
    };

    loadA(0, 0);
    CP_COMMIT();

    int lane = tid & 31, warp = tid >> 5;
    int wm = warp & 3;   // 32 m-rows
    int wn = warp >> 2;  // 64 n-cols

    // ldmatrix lane addresses (byte offsets sans buffer base / k-step)
    int arow = wm * 32 + (lane & 15);
    int acol2 = ((lane >> 4) << 3) * 2;
    uint32_t aoff0 = (uint32_t)(arow * 272 + acol2);
    uint32_t aoff1 = (uint32_t)((arow + 16) * 272 + acol2);
    int brow = wn * 64 + (lane & 7) + ((lane >> 4) << 3);
    int bcol2 = (((lane >> 3) & 1) << 3) * 2;
    uint32_t boff0 = (uint32_t)(brow * 272 + bcol2);

    const int l4 = lane >> 2, lm = lane & 3;

    for (int it = 0; it < 16; it++) {
        if (it + 1 < 16) loadA(it + 1, (it + 1) & 1);
        CP_COMMIT();
        CP_WAIT1();
        __syncthreads();

        uint32_t abase = sb + ((it & 1) ? SMA1 : SMA0);
        uint32_t bbase = sb + SMB;

        float acc[2][8][4];
#pragma unroll
        for (int mt = 0; mt < 2; mt++)
#pragma unroll
            for (int nt = 0; nt < 8; nt++)
#pragma unroll
                for (int r = 0; r < 4; r++) acc[mt][nt][r] = 0.f;

#pragma unroll
        for (int s = 0; s < 8; s++) {
            uint32_t kb = (uint32_t)s * 32;  // 16 halfs
            uint32_t a0[4], a1[4];
            LDSM_X4(a0[0], a0[1], a0[2], a0[3], abase + aoff0 + kb);
            LDSM_X4(a1[0], a1[1], a1[2], a1[3], abase + aoff1 + kb);
#pragma unroll
            for (int np = 0; np < 4; np++) {
                uint32_t b0, b1, b2, b3;
                LDSM_X4(b0, b1, b2, b3, bbase + boff0 + (uint32_t)np * (16 * 272) + kb);
                HMMA16(acc[0][np * 2],     a0, b0, b1);
                HMMA16(acc[1][np * 2],     a1, b0, b1);
                HMMA16(acc[0][np * 2 + 1], a0, b2, b3);
                HMMA16(acc[1][np * 2 + 1], a1, b2, b3);
            }
        }

        // Epilogue: half2 complex writes
        int b0r = it * 128;
#pragma unroll
        for (int mt = 0; mt < 2; mt++) {
            int mrow = wm * 32 + mt * 16 + l4;
            size_t base0 = ((size_t)(b0r + mrow) * KH + f) * KOUT;
            size_t base1 = base0 + (size_t)8 * KH * KOUT;
#pragma unroll
            for (int nt = 0; nt < 8; nt++) {
                int i = wn * 32 + nt * 4 + lm;
                g_Yh[base0 + i] = __floats2half2_rn(acc[mt][nt][0], acc[mt][nt][1]);
                g_Yh[base1 + i] = __floats2half2_rn(acc[mt][nt][2], acc[mt][nt][3]);
            }
        }
        __syncthreads(); // buffer consumed before next overwrite
    }
}

// ---------------------------------------------------------------------------
// Kernel 4: inverse rFFT, real output, scale 1/256.
// ---------------------------------------------------------------------------
__global__ __launch_bounds__(256) void fft_inv(float* __restrict__ out) {
    __shared__ float2 tw[256];
    __shared__ float2 sbuf[16 * 16 * 17];

    const int rev[16] = REV4_LIST;
    int tid = threadIdx.x;
    {
        float s, c;
        sincospif(-(float)tid * (1.0f / 128.0f), &s, &c);
        tw[tid] = make_float2(c, s);
    }
    int cta = blockIdx.x;
    int b  = cta >> 2;
    int i0 = (cta & 3) << 4;
    int g  = tid >> 4;
    int t  = tid & 15;

    for (int k = tid; k < 129 * 16; k += 256) {
        int gg = k & 15;
        int f  = k >> 4;
        sbuf[f * 17 + gg] = __half22float2(g_Yh[((size_t)b * KH + f) * KOUT + i0 + gg]);
    }
    __syncthreads();

    int f1 = t;
    float2 a[16];
#pragma unroll
    for (int f2 = 0; f2 < 16; f2++) {
        int f = f1 + (f2 << 4);
        if (f <= 128) {
            a[f2] = sbuf[f * 17 + g];
        } else {
            float2 v = sbuf[(256 - f) * 17 + g];
            a[f2] = make_float2(v.x, -v.y);
        }
    }
    __syncthreads();

    fft16_full<true>(a);
#pragma unroll
    for (int t1 = 0; t1 < 16; t1++) {
        float2 B = a[rev[t1]];
        float2 t2 = tw[(f1 * t1) & 255];
        float pr =  B.x * t2.x + B.y * t2.y;
        float pi = -B.x * t2.y + B.y * t2.x;
        sbuf[g * 272 + f1 * 17 + t1] = make_float2(pr, pi);
    }
    __syncthreads();

    int t1 = t;
    float2 bb[16];
#pragma unroll
    for (int f1i = 0; f1i < 16; f1i++) bb[f1i] = sbuf[g * 272 + f1i * 17 + t1];
    __syncthreads();

    fft16_full<true>(bb);

    float* outs = (float*)sbuf;
#pragma unroll
    for (int t2 = 0; t2 < 16; t2++) {
        outs[g * 256 + t1 + (t2 << 4)] = bb[rev[t2]].x * (1.0f / 256.0f);
    }
    __syncthreads();

    float* op = out + (size_t)b * 16384 + (size_t)i0 * 256;
    for (int k = tid; k < 4096; k += 256) op[k] = outs[k];
}

// ---------------------------------------------------------------------------
extern "C" void kernel_launch(void* const* d_in, const int* in_sizes, int n_in,
                              void* d_out, int out_size) {
    const float* x  = (const float*)d_in[0];
    const float* Wr = (const float*)d_in[1];
    const float* Wi = (const float*)d_in[2];
    float* out = (float*)d_out;

    cudaFuncSetAttribute(cgemm_h, cudaFuncAttributeMaxDynamicSharedMemorySize, SMTOT);

    prep_b<<<(KH * 16384 + 255) / 256, 256>>>(Wr, Wi);
    fft_fwd<<<B_SZ * (KIN / 16), 256>>>(x);
    cgemm_h<<<KH, 256, SMTOT>>>();
    fft_inv<<<B_SZ * (KOUT / 16), 256>>>(out);
}